// round 13
// baseline (speedup 1.0000x reference)
#include <cuda_runtime.h>
#include <math.h>

#define BATCH 8
#define NPTS  4096
#define KNN   20
#define TPB   512                  // 16 warps
#define Q     4                    // queries per warp
#define QPB   (TPB / 32 * Q)       // 64 queries per block
#define BPB   (NPTS / QPB)         // 64 blocks per batch
#define E_TOTAL (BATCH * NPTS * KNN)
#define FULL 0xffffffffu

__global__ __launch_bounds__(TPB, 3)
void knn_kernel(const float* __restrict__ pc, float* __restrict__ out) {
    extern __shared__ float4 spts[];           // 4096 x (x,y,z, 0.5*||p||^2) = 64 KB

    const int b    = blockIdx.x / BPB;
    const int jb   = blockIdx.x % BPB;
    const int tid  = threadIdx.x;
    const int wid  = tid >> 5;
    const int lane = tid & 31;

    // Stage this batch's points into smem
    const float* base = pc + (size_t)b * NPTS * 3;
    for (int j = tid; j < NPTS; j += TPB) {
        float x = base[3 * j], y = base[3 * j + 1], z = base[3 * j + 2];
        spts[j] = make_float4(x, y, z, 0.5f * (x * x + y * y + z * z));
    }
    __syncthreads();

    // This warp's Q consecutive queries (q.w reloaded at epilogue; smem stays intact)
    const int i0 = jb * QPB + wid * Q;
    float qx[Q], qy[Q], qz[Q];
#pragma unroll
    for (int t = 0; t < Q; ++t) {
        float4 qt = spts[i0 + t];              // lane-uniform -> broadcast
        qx[t] = qt.x; qy[t] = qt.y; qz[t] = qt.z;
    }

    // Per-query warp-distributed sorted list: lane l holds l-th smallest e.
    // e = 0.5||p||^2 - q.p (monotone in d2, exact-float ordering).
    float held[Q]; int hidx[Q]; float thr[Q];
#pragma unroll
    for (int t = 0; t < Q; ++t) { held[t] = 3.0e38f; hidx[t] = 0x7fffffff; thr[t] = 3.0e38f; }

    for (int c0 = 0; c0 < NPTS; c0 += 32) {
        const float4 p = spts[c0 + lane];      // ONE load feeds Q queries
        const int j = c0 + lane;
        float e[Q]; bool pr[Q]; bool anyp = false;
#pragma unroll
        for (int t = 0; t < Q; ++t) {
            e[t] = fmaf(-qx[t], p.x, fmaf(-qy[t], p.y, fmaf(-qz[t], p.z, p.w)));
            pr[t] = (e[t] < thr[t]) && (j != i0 + t);
            anyp |= pr[t];
        }
        if (__any_sync(FULL, anyp)) {          // slow path (per-query ballots)
#pragma unroll
            for (int t = 0; t < Q; ++t) {
                unsigned m = __ballot_sync(FULL, pr[t]);
                while (m) {
                    const int src = __ffs(m) - 1;
                    m &= m - 1;
                    const float v = __shfl_sync(FULL, e[t], src);
                    if (v < thr[t]) {          // recheck: thr tightens within batch
                        const int vj = c0 + src;
                        bool keep = (held[t] <= v);   // ties: earlier j stays first
                        unsigned bm = __ballot_sync(FULL, keep);
                        float up_v = __shfl_up_sync(FULL, held[t], 1);
                        int   up_i = __shfl_up_sync(FULL, hidx[t], 1);
                        bool prevkeep = (lane == 0) ? true : ((bm >> (lane - 1)) & 1u);
                        if (!keep) {
                            held[t] = prevkeep ? v  : up_v;
                            hidx[t] = prevkeep ? vj : up_i;
                        }
                        thr[t] = __shfl_sync(FULL, held[t], KNN - 1);
                    }
                }
            }
        }
    }

    // Epilogue: lanes 0..19 of held[t] are the sorted top-20 for query i0+t.
#pragma unroll
    for (int t = 0; t < Q; ++t) {
        const int   i      = i0 + t;
        const float qw     = spts[i].w;                      // 0.5*||q||^2 (broadcast)
        const float eK     = __shfl_sync(FULL, held[t], KNN - 1);
        const float d2K    = fmaxf(2.0f * (qw + eK), 0.0f);
        const float dk     = sqrtf(d2K);
        const float sigma  = dk + 1e-6f;
        const float inv2s2 = 1.0f / (2.0f * sigma * sigma);
        const int   gi     = b * NPTS + i;
        const int   ebase  = gi * KNN;

        if (lane < KNN) {
            float d2 = fmaxf(2.0f * (qw + held[t]), 0.0f);
            out[ebase + lane]               = (float)gi;                 // src
            out[E_TOTAL + ebase + lane]     = (float)(b * NPTS + hidx[t]); // tgt
            out[2 * E_TOTAL + ebase + lane] = expf(-d2 * inv2s2);        // attrs
        }
        if (lane == 0)
            out[3 * E_TOTAL + gi] = dk * dk;                             // s_local
    }
}

extern "C" void kernel_launch(void* const* d_in, const int* in_sizes, int n_in,
                              void* d_out, int out_size) {
    (void)in_sizes; (void)n_in; (void)out_size;
    const float* pc  = (const float*)d_in[0];
    float*       out = (float*)d_out;

    const int smem = NPTS * sizeof(float4);    // 64 KB
    cudaFuncSetAttribute(knn_kernel,
                         cudaFuncAttributeMaxDynamicSharedMemorySize, smem);

    dim3 grid(BATCH * BPB);                    // 512 blocks, 64 queries each
    knn_kernel<<<grid, TPB, smem>>>(pc, out);
}

// round 14
// speedup vs baseline: 1.1353x; 1.1353x over previous
#include <cuda_runtime.h>
#include <math.h>

#define BATCH 8
#define NPTS  4096
#define KNN   20
#define TPB   512                  // 16 warps = 16 queries per block
#define WPB   (TPB / 32)
#define BPB   (NPTS / WPB)         // 256 blocks per batch
#define TILE  256                  // candidates per outer iteration (8 x 32)
#define E_TOTAL (BATCH * NPTS * KNN)
#define FULL 0xffffffffu

__global__ __launch_bounds__(TPB, 3)
void knn_kernel(const float* __restrict__ pc, float* __restrict__ out) {
    extern __shared__ float4 spts[];           // 4096 x (x,y,z, 0.5*||p||^2) = 64 KB

    const int b    = blockIdx.x / BPB;
    const int jb   = blockIdx.x % BPB;
    const int tid  = threadIdx.x;
    const int wid  = tid >> 5;
    const int lane = tid & 31;

    // Stage this batch's points into smem
    const float* base = pc + (size_t)b * NPTS * 3;
    for (int j = tid; j < NPTS; j += TPB) {
        float x = base[3 * j], y = base[3 * j + 1], z = base[3 * j + 2];
        spts[j] = make_float4(x, y, z, 0.5f * (x * x + y * y + z * z));
    }
    __syncthreads();

    const int i = jb * WPB + wid;              // this warp's query
    const float4 q = spts[i];                  // lane-uniform -> broadcast

    // Warp-distributed sorted list: lane l holds l-th smallest e seen.
    // e = 0.5||p||^2 - q.p (monotone in d2, exact-float ordering).
    float held = 3.0e38f;
    int   hidx = 0x7fffffff;
    float thr  = 3.0e38f;                      // lane-19 value (20th smallest)

    for (int c0 = 0; c0 < NPTS; c0 += TILE) {
        float e[8];
#pragma unroll
        for (int u = 0; u < 8; ++u) {
            float4 p = spts[c0 + u * 32 + lane];
            e[u] = fmaf(-q.x, p.x, fmaf(-q.y, p.y, fmaf(-q.z, p.z, p.w)));
        }
        // min-reduce trigger (no self-check here: self's e is ultra-negative,
        // its tile simply triggers and the pop loop skips vj == i)
        float m0 = fminf(fminf(e[0], e[1]), fminf(e[2], e[3]));
        float m1 = fminf(fminf(e[4], e[5]), fminf(e[6], e[7]));
        float mn = fminf(m0, m1);

        if (__any_sync(FULL, mn < thr)) {      // slow path
#pragma unroll
            for (int u = 0; u < 8; ++u) {
                unsigned m = __ballot_sync(FULL, e[u] < thr);
                const int jb0 = c0 + u * 32;
                while (m) {
                    const int src = __ffs(m) - 1;
                    m &= m - 1;
                    const float v  = __shfl_sync(FULL, e[u], src);
                    const int   vj = jb0 + src;
                    if (v < thr && vj != i) {  // recheck (thr tightens) + self skip
                        // warp-parallel sorted insert (shift-by-one above pos)
                        bool keep = (held <= v);   // ties: earlier j stays first
                        unsigned bm = __ballot_sync(FULL, keep);
                        float up_v = __shfl_up_sync(FULL, held, 1);
                        int   up_i = __shfl_up_sync(FULL, hidx, 1);
                        bool prevkeep = (lane == 0) ? true : ((bm >> (lane - 1)) & 1u);
                        if (!keep) {
                            held = prevkeep ? v  : up_v;
                            hidx = prevkeep ? vj : up_i;
                        }
                        thr = __shfl_sync(FULL, held, KNN - 1);
                    }
                }
            }
        }
    }

    // Epilogue: lanes 0..19 hold the sorted top-20 (e ascending, ties by j).
    const float d2K    = fmaxf(2.0f * (q.w + thr), 0.0f);
    const float dk     = sqrtf(d2K);
    const float sigma  = dk + 1e-6f;
    const float inv2s2 = 1.0f / (2.0f * sigma * sigma);

    const int gi    = b * NPTS + i;
    const int ebase = gi * KNN;

    if (lane < KNN) {
        float d2 = fmaxf(2.0f * (q.w + held), 0.0f);
        out[ebase + lane]               = (float)gi;                    // src
        out[E_TOTAL + ebase + lane]     = (float)(b * NPTS + hidx);     // tgt
        out[2 * E_TOTAL + ebase + lane] = expf(-d2 * inv2s2);           // attrs
    }
    if (lane == 0)
        out[3 * E_TOTAL + gi] = dk * dk;                                // s_local
}

extern "C" void kernel_launch(void* const* d_in, const int* in_sizes, int n_in,
                              void* d_out, int out_size) {
    (void)in_sizes; (void)n_in; (void)out_size;
    const float* pc  = (const float*)d_in[0];
    float*       out = (float*)d_out;

    const int smem = NPTS * sizeof(float4);    // 64 KB
    cudaFuncSetAttribute(knn_kernel,
                         cudaFuncAttributeMaxDynamicSharedMemorySize, smem);

    dim3 grid(BATCH * BPB);                    // 2048 blocks, 16 queries each
    knn_kernel<<<grid, TPB, smem>>>(pc, out);
}

// round 15
// speedup vs baseline: 1.4979x; 1.3194x over previous
#include <cuda_runtime.h>
#include <math.h>

#define BATCH 8
#define NPTS  4096
#define KNN   20
#define TPB   512                  // 16 warps = 16 queries per block
#define WPB   (TPB / 32)
#define BPB   (NPTS / WPB)         // 256 blocks per batch
#define E_TOTAL (BATCH * NPTS * KNN)
#define FULL 0xffffffffu

__global__ __launch_bounds__(TPB, 2)
void knn_kernel(const float* __restrict__ pc, float* __restrict__ out) {
    extern __shared__ float4 spts[];           // 4096 x (x,y,z, 0.5*||p||^2) = 64 KB

    const int b    = blockIdx.x / BPB;
    const int jb   = blockIdx.x % BPB;
    const int tid  = threadIdx.x;
    const int wid  = tid >> 5;
    const int lane = tid & 31;

    // Stage this batch's points into smem
    const float* base = pc + (size_t)b * NPTS * 3;
    for (int j = tid; j < NPTS; j += TPB) {
        float x = base[3 * j], y = base[3 * j + 1], z = base[3 * j + 2];
        spts[j] = make_float4(x, y, z, 0.5f * (x * x + y * y + z * z));
    }
    __syncthreads();

    const int i = jb * WPB + wid;              // this warp's query
    const float4 q = spts[i];                  // lane-uniform -> broadcast

    // ---- Bitonic init: fully sort candidates j = 0..31 by (e, j) ascending ----
    // e = 0.5||p||^2 - q.p (monotone in d2, exact-float ordering).
    float held;
    int   hidx = lane;
    {
        float4 p = spts[lane];
        held = fmaf(-q.x, p.x, fmaf(-q.y, p.y, fmaf(-q.z, p.z, p.w)));
        if (lane == i) held = 3.0e38f;         // self sorts last (i<32 only when jb<2)
    }
#pragma unroll
    for (int k = 2; k <= 32; k <<= 1) {
#pragma unroll
        for (int s = k >> 1; s > 0; s >>= 1) {
            float pe = __shfl_xor_sync(FULL, held, s);
            int   pi = __shfl_xor_sync(FULL, hidx, s);
            bool pless    = (pe < held) || (pe == held && pi < hidx);
            bool iam_low  = !(lane & s);
            bool up       = !(lane & k) || (k == 32);
            bool keep_min = (up == iam_low);
            if (keep_min == pless) { held = pe; hidx = pi; }
        }
    }
    float thr = __shfl_sync(FULL, held, KNN - 1);   // 20th smallest so far

    // ---- First tile's remaining subgroups (j = 32..127), standard path ----
#pragma unroll
    for (int u = 1; u < 4; ++u) {
        const int jb0 = u * 32;
        const int j = jb0 + lane;
        float4 p = spts[j];
        float ev = fmaf(-q.x, p.x, fmaf(-q.y, p.y, fmaf(-q.z, p.z, p.w)));
        unsigned m = __ballot_sync(FULL, (ev < thr) && (j != i));
        while (m) {
            const int src = __ffs(m) - 1;
            m &= m - 1;
            const float v = __shfl_sync(FULL, ev, src);
            if (v < thr) {
                const int vj = jb0 + src;
                bool keep = (held <= v);
                unsigned bm = __ballot_sync(FULL, keep);
                float up_v = __shfl_up_sync(FULL, held, 1);
                int   up_i = __shfl_up_sync(FULL, hidx, 1);
                bool prevkeep = (lane == 0) ? true : ((bm >> (lane - 1)) & 1u);
                if (!keep) {
                    held = prevkeep ? v  : up_v;
                    hidx = prevkeep ? vj : up_i;
                }
                thr = __shfl_sync(FULL, held, KNN - 1);
            }
        }
    }

    // ---- Main loop (identical to R12), candidates 128..4095 ----
    for (int c0 = 128; c0 < NPTS; c0 += 128) {
        float e0, e1, e2, e3;
        bool  p0, p1, p2, p3;
        {
            float4 a  = spts[c0 + lane];
            float4 bb = spts[c0 + 32 + lane];
            float4 c  = spts[c0 + 64 + lane];
            float4 d  = spts[c0 + 96 + lane];
            e0 = fmaf(-q.x, a.x,  fmaf(-q.y, a.y,  fmaf(-q.z, a.z,  a.w)));
            e1 = fmaf(-q.x, bb.x, fmaf(-q.y, bb.y, fmaf(-q.z, bb.z, bb.w)));
            e2 = fmaf(-q.x, c.x,  fmaf(-q.y, c.y,  fmaf(-q.z, c.z,  c.w)));
            e3 = fmaf(-q.x, d.x,  fmaf(-q.y, d.y,  fmaf(-q.z, d.z,  d.w)));
            p0 = (e0 < thr) && (c0 + lane      != i);
            p1 = (e1 < thr) && (c0 + 32 + lane != i);
            p2 = (e2 < thr) && (c0 + 64 + lane != i);
            p3 = (e3 < thr) && (c0 + 96 + lane != i);
        }
        if (__any_sync(FULL, p0 | p1 | p2 | p3)) {
#pragma unroll
            for (int u = 0; u < 4; ++u) {
                bool  pu = (u == 0) ? p0 : (u == 1) ? p1 : (u == 2) ? p2 : p3;
                float eu = (u == 0) ? e0 : (u == 1) ? e1 : (u == 2) ? e2 : e3;
                unsigned m = __ballot_sync(FULL, pu);
                const int jb0 = c0 + u * 32;
                while (m) {
                    const int src = __ffs(m) - 1;
                    m &= m - 1;
                    const float v = __shfl_sync(FULL, eu, src);
                    if (v < thr) {                 // recheck (thr tightens)
                        const int vj = jb0 + src;
                        bool keep = (held <= v);   // ties: earlier j stays first
                        unsigned bm = __ballot_sync(FULL, keep);
                        float up_v = __shfl_up_sync(FULL, held, 1);
                        int   up_i = __shfl_up_sync(FULL, hidx, 1);
                        bool prevkeep = (lane == 0) ? true : ((bm >> (lane - 1)) & 1u);
                        if (!keep) {
                            held = prevkeep ? v  : up_v;
                            hidx = prevkeep ? vj : up_i;
                        }
                        thr = __shfl_sync(FULL, held, KNN - 1);
                    }
                }
            }
        }
    }

    // Epilogue: lanes 0..19 hold the sorted top-20 (e ascending, ties by j).
    const float d2K    = fmaxf(2.0f * (q.w + thr), 0.0f);
    const float dk     = sqrtf(d2K);
    const float sigma  = dk + 1e-6f;
    const float inv2s2 = 1.0f / (2.0f * sigma * sigma);

    const int gi    = b * NPTS + i;
    const int ebase = gi * KNN;

    if (lane < KNN) {
        float d2 = fmaxf(2.0f * (q.w + held), 0.0f);
        out[ebase + lane]               = (float)gi;                    // src
        out[E_TOTAL + ebase + lane]     = (float)(b * NPTS + hidx);     // tgt
        out[2 * E_TOTAL + ebase + lane] = expf(-d2 * inv2s2);           // attrs
    }
    if (lane == 0)
        out[3 * E_TOTAL + gi] = dk * dk;                                // s_local
}

extern "C" void kernel_launch(void* const* d_in, const int* in_sizes, int n_in,
                              void* d_out, int out_size) {
    (void)in_sizes; (void)n_in; (void)out_size;
    const float* pc  = (const float*)d_in[0];
    float*       out = (float*)d_out;

    const int smem = NPTS * sizeof(float4);    // 64 KB
    cudaFuncSetAttribute(knn_kernel,
                         cudaFuncAttributeMaxDynamicSharedMemorySize, smem);

    dim3 grid(BATCH * BPB);                    // 2048 blocks, 16 queries each
    knn_kernel<<<grid, TPB, smem>>>(pc, out);
}

// round 17
// speedup vs baseline: 1.5483x; 1.0336x over previous
#include <cuda_runtime.h>
#include <math.h>

#define BATCH 8
#define NPTS  4096
#define KNN   20
#define TPB   1024                 // 32 warps = 32 queries per block
#define WPB   (TPB / 32)
#define BPB   (NPTS / WPB)         // 128 blocks per batch
#define E_TOTAL (BATCH * NPTS * KNN)
#define FULL 0xffffffffu

__global__ __launch_bounds__(TPB, 2)
void knn_kernel(const float* __restrict__ pc, float* __restrict__ out) {
    extern __shared__ float4 spts[];           // 4096 x (x,y,z, 0.5*||p||^2) = 64 KB

    const int b    = blockIdx.x / BPB;
    const int jb   = blockIdx.x % BPB;
    const int tid  = threadIdx.x;
    const int wid  = tid >> 5;
    const int lane = tid & 31;

    // Stage this batch's points into smem
    const float* base = pc + (size_t)b * NPTS * 3;
    for (int j = tid; j < NPTS; j += TPB) {
        float x = base[3 * j], y = base[3 * j + 1], z = base[3 * j + 2];
        spts[j] = make_float4(x, y, z, 0.5f * (x * x + y * y + z * z));
    }
    __syncthreads();

    const int i = jb * WPB + wid;              // this warp's query
    const float4 q = spts[i];                  // lane-uniform -> broadcast

    // ---- Bitonic init: fully sort candidates j = 0..31 by (e, j) ascending ----
    // e = 0.5||p||^2 - q.p (monotone in d2, exact-float ordering).
    float held;
    int   hidx = lane;
    {
        float4 p = spts[lane];
        held = fmaf(-q.x, p.x, fmaf(-q.y, p.y, fmaf(-q.z, p.z, p.w)));
        if (lane == i) held = 3.0e38f;         // self sorts last (i<32 only when jb==0)
    }
#pragma unroll
    for (int k = 2; k <= 32; k <<= 1) {
#pragma unroll
        for (int s = k >> 1; s > 0; s >>= 1) {
            float pe = __shfl_xor_sync(FULL, held, s);
            int   pi = __shfl_xor_sync(FULL, hidx, s);
            bool pless    = (pe < held) || (pe == held && pi < hidx);
            bool iam_low  = !(lane & s);
            bool up       = !(lane & k) || (k == 32);
            bool keep_min = (up == iam_low);
            if (keep_min == pless) { held = pe; hidx = pi; }
        }
    }
    float thr = __shfl_sync(FULL, held, KNN - 1);   // 20th smallest so far

    // ---- First tile's remaining subgroups (j = 32..127), standard path ----
#pragma unroll
    for (int u = 1; u < 4; ++u) {
        const int jb0 = u * 32;
        const int j = jb0 + lane;
        float4 p = spts[j];
        float ev = fmaf(-q.x, p.x, fmaf(-q.y, p.y, fmaf(-q.z, p.z, p.w)));
        unsigned m = __ballot_sync(FULL, (ev < thr) && (j != i));
        while (m) {
            const int src = __ffs(m) - 1;
            m &= m - 1;
            const float v = __shfl_sync(FULL, ev, src);
            if (v < thr) {
                const int vj = jb0 + src;
                bool keep = (held <= v);
                unsigned bm = __ballot_sync(FULL, keep);
                float up_v = __shfl_up_sync(FULL, held, 1);
                int   up_i = __shfl_up_sync(FULL, hidx, 1);
                bool prevkeep = (lane == 0) ? true : ((bm >> (lane - 1)) & 1u);
                if (!keep) {
                    held = prevkeep ? v  : up_v;
                    hidx = prevkeep ? vj : up_i;
                }
                thr = __shfl_sync(FULL, held, KNN - 1);
            }
        }
    }

    // ---- Main loop, candidates 128..4095 ----
    for (int c0 = 128; c0 < NPTS; c0 += 128) {
        float e0, e1, e2, e3;
        bool  p0, p1, p2, p3;
        {
            float4 a  = spts[c0 + lane];
            float4 bb = spts[c0 + 32 + lane];
            float4 c  = spts[c0 + 64 + lane];
            float4 d  = spts[c0 + 96 + lane];
            e0 = fmaf(-q.x, a.x,  fmaf(-q.y, a.y,  fmaf(-q.z, a.z,  a.w)));
            e1 = fmaf(-q.x, bb.x, fmaf(-q.y, bb.y, fmaf(-q.z, bb.z, bb.w)));
            e2 = fmaf(-q.x, c.x,  fmaf(-q.y, c.y,  fmaf(-q.z, c.z,  c.w)));
            e3 = fmaf(-q.x, d.x,  fmaf(-q.y, d.y,  fmaf(-q.z, d.z,  d.w)));
            p0 = (e0 < thr) && (c0 + lane      != i);
            p1 = (e1 < thr) && (c0 + 32 + lane != i);
            p2 = (e2 < thr) && (c0 + 64 + lane != i);
            p3 = (e3 < thr) && (c0 + 96 + lane != i);
        }
        if (__any_sync(FULL, p0 | p1 | p2 | p3)) {
#pragma unroll
            for (int u = 0; u < 4; ++u) {
                bool  pu = (u == 0) ? p0 : (u == 1) ? p1 : (u == 2) ? p2 : p3;
                float eu = (u == 0) ? e0 : (u == 1) ? e1 : (u == 2) ? e2 : e3;
                unsigned m = __ballot_sync(FULL, pu);
                const int jb0 = c0 + u * 32;
                while (m) {
                    const int src = __ffs(m) - 1;
                    m &= m - 1;
                    const float v = __shfl_sync(FULL, eu, src);
                    if (v < thr) {                 // recheck (thr tightens)
                        const int vj = jb0 + src;
                        bool keep = (held <= v);   // ties: earlier j stays first
                        unsigned bm = __ballot_sync(FULL, keep);
                        float up_v = __shfl_up_sync(FULL, held, 1);
                        int   up_i = __shfl_up_sync(FULL, hidx, 1);
                        bool prevkeep = (lane == 0) ? true : ((bm >> (lane - 1)) & 1u);
                        if (!keep) {
                            held = prevkeep ? v  : up_v;
                            hidx = prevkeep ? vj : up_i;
                        }
                        thr = __shfl_sync(FULL, held, KNN - 1);
                    }
                }
            }
        }
    }

    // Epilogue: lanes 0..19 hold the sorted top-20 (e ascending, ties by j).
    const float d2K    = fmaxf(2.0f * (q.w + thr), 0.0f);
    const float dk     = sqrtf(d2K);
    const float sigma  = dk + 1e-6f;
    const float inv2s2 = 1.0f / (2.0f * sigma * sigma);

    const int gi    = b * NPTS + i;
    const int ebase = gi * KNN;

    if (lane < KNN) {
        float d2 = fmaxf(2.0f * (q.w + held), 0.0f);
        out[ebase + lane]               = (float)gi;                    // src
        out[E_TOTAL + ebase + lane]     = (float)(b * NPTS + hidx);     // tgt
        out[2 * E_TOTAL + ebase + lane] = expf(-d2 * inv2s2);           // attrs
    }
    if (lane == 0)
        out[3 * E_TOTAL + gi] = dk * dk;                                // s_local
}

extern "C" void kernel_launch(void* const* d_in, const int* in_sizes, int n_in,
                              void* d_out, int out_size) {
    (void)in_sizes; (void)n_in; (void)out_size;
    const float* pc  = (const float*)d_in[0];
    float*       out = (float*)d_out;

    const int smem = NPTS * sizeof(float4);    // 64 KB
    cudaFuncSetAttribute(knn_kernel,
                         cudaFuncAttributeMaxDynamicSharedMemorySize, smem);
    cudaFuncSetAttribute(knn_kernel,
                         cudaFuncAttributePreferredSharedMemoryCarveout, 100);

    dim3 grid(BATCH * BPB);                    // 1024 blocks, 32 queries each
    knn_kernel<<<grid, TPB, smem>>>(pc, out);
}